// round 16
// baseline (speedup 1.0000x reference)
#include <cuda_runtime.h>
#include <cuda_bf16.h>
#include <cstdint>
#include <math.h>

// Problem constants
#define BSZ   8192
#define TT    3
#define HH    256
#define RELN  2000
#define OUTQ  (24576*256)   // one output quarter (T*B, H)

// ---------------- device scratch (no allocs allowed) ----------------
__device__ float g_Wsub[256*512];    // [W1 | W1*WgT]
__device__ float g_Wrel[256*512];    // [W4 | W4*WgB]
__device__ float g_Wh  [256*1024];   // [W2 | W3 | W2*WgB | W3*WgT]
__device__ float g_brel[512];        // [b4 | 0]
__device__ float g_bh  [1024];       // [b2 | 0 | 0 | 0]
__device__ float g_bgc1[256];        // bg + b2@WgB
__device__ float g_bgc2[256];        // bg + b4@WgB
__device__ float g_RelTab[RELN*512]; // rel_embed @ g_Wrel + g_brel
__device__ float g_SA  [24576*512];  // per-direction: sub-emb @ g_Wsub  (t-major rows)
__device__ float g_HQ  [8192*1024];  // h @ g_Wh + g_bh
__device__ float g_op1 [8192*256];
__device__ float g_P   [8192*256];   // op1 @ W5
__device__ float g_hbuf[8192*256];   // carry h (= op2)

// ---------------- small weight-combine kernels ----------------
__global__ void combine_weights(const float* __restrict__ W1, const float* __restrict__ W2,
                                const float* __restrict__ W3, const float* __restrict__ W4,
                                const float* __restrict__ Wg)
{
    __shared__ float sA[32][33];
    __shared__ float sG[32][33];
    int tx = threadIdx.x, ty = threadIdx.y;
    int jb = blockIdx.x*32, ib = blockIdx.y*32, z = blockIdx.z;
    const float* Wa; float* dst; int dstN, dcol, wgbase; bool prod;
    switch(z){
      case 0: dst=g_Wsub; dstN=512;  dcol=0;   Wa=W1; prod=false; wgbase=0;   break;
      case 1: dst=g_Wsub; dstN=512;  dcol=256; Wa=W1; prod=true;  wgbase=0;   break;
      case 2: dst=g_Wrel; dstN=512;  dcol=0;   Wa=W4; prod=false; wgbase=0;   break;
      case 3: dst=g_Wrel; dstN=512;  dcol=256; Wa=W4; prod=true;  wgbase=256; break;
      case 4: dst=g_Wh;   dstN=1024; dcol=0;   Wa=W2; prod=false; wgbase=0;   break;
      case 5: dst=g_Wh;   dstN=1024; dcol=256; Wa=W3; prod=false; wgbase=0;   break;
      case 6: dst=g_Wh;   dstN=1024; dcol=512; Wa=W2; prod=true;  wgbase=256; break;
      default:dst=g_Wh;   dstN=1024; dcol=768; Wa=W3; prod=true;  wgbase=0;   break;
    }
    if (!prod){
        dst[(ib+ty)*dstN + dcol + jb + tx] = Wa[(ib+ty)*256 + jb + tx];
        return;
    }
    float acc = 0.f;
    for (int kb=0; kb<256; kb+=32){
        sA[ty][tx] = Wa[(ib+ty)*256 + kb + tx];
        sG[ty][tx] = Wg[(size_t)(wgbase+kb+ty)*256 + jb + tx];
        __syncthreads();
        #pragma unroll
        for (int kk=0; kk<32; kk++) acc += sA[ty][kk]*sG[kk][tx];
        __syncthreads();
    }
    dst[(ib+ty)*dstN + dcol + jb + tx] = acc;
}

__global__ void bias_combine(const float* __restrict__ b2, const float* __restrict__ b4,
                             const float* __restrict__ bg, const float* __restrict__ Wg)
{
    int j = threadIdx.x;
    float s1 = bg[j], s2 = bg[j];
    for (int k=0; k<256; k++){
        float w = Wg[(size_t)(256+k)*256 + j];
        s1 += b2[k]*w;
        s2 += b4[k]*w;
    }
    g_bgc1[j]=s1; g_bgc2[j]=s2;
    g_bh[j]=b2[j]; g_bh[256+j]=0.f; g_bh[512+j]=0.f; g_bh[768+j]=0.f;
    g_brel[j]=b4[j]; g_brel[256+j]=0.f;
}

// ---------------- 3xTF32 tensor-core GEMM (K=256 fixed) ----------------
// fp32 accuracy via hi/lo split: acc += ah*bh + ah*bl + al*bh
#define BM 128
#define BN 128
#define BK 32
#define SA_ST 40     // 128x32 A tile, padded stride -> conflict-free frag loads
#define SB_ST 136    // 32x128 B tile
#define SMEM_BYTES ((2*BM*SA_ST + 2*BK*SB_ST)*4)

__device__ __forceinline__ void cp16(float* dst, const float* src, int sz){
    uint32_t d = (uint32_t)__cvta_generic_to_shared(dst);
    asm volatile("cp.async.ca.shared.global [%0], [%1], 16, %2;\n" :: "r"(d), "l"(src), "r"(sz));
}
__device__ __forceinline__ void cp_commit(){ asm volatile("cp.async.commit_group;\n"); }
template<int NG> __device__ __forceinline__ void cp_wait(){ asm volatile("cp.async.wait_group %0;\n"::"n"(NG)); }

__device__ __forceinline__ uint32_t f2tf(float f){
    uint32_t r; asm("cvt.rna.tf32.f32 %0, %1;" : "=r"(r) : "f"(f)); return r;
}
__device__ __forceinline__ void split_tf(float v, uint32_t& hi, uint32_t& lo){
    hi = f2tf(v);
    lo = f2tf(v - __uint_as_float(hi));
}

__device__ __forceinline__ void mma8(float* c, const uint32_t* a, const uint32_t* b){
    asm volatile("mma.sync.aligned.m16n8k8.row.col.f32.tf32.tf32.f32 "
        "{%0,%1,%2,%3},{%4,%5,%6,%7},{%8,%9},{%0,%1,%2,%3};\n"
        : "+f"(c[0]),"+f"(c[1]),"+f"(c[2]),"+f"(c[3])
        : "r"(a[0]),"r"(a[1]),"r"(a[2]),"r"(a[3]),"r"(b[0]),"r"(b[1]));
}

// GATHER==0: A rows direct (lda=256).  GATHER==1: row r -> t=r>>13,b=r&8191, A row = table[seqs[b*7+2t]]
template<int GATHER>
__global__ __launch_bounds__(256,1) void gemm_tf32(
    const float* __restrict__ A, const int* __restrict__ seqs, const float* __restrict__ table,
    const float* __restrict__ W, const float* __restrict__ bias, const float* __restrict__ mulsrc,
    float* __restrict__ C, int M, int N)
{
    extern __shared__ float smem[];
    float* As = smem;
    float* Bs = smem + 2*BM*SA_ST;
    int tid  = threadIdx.x;
    int lane = tid & 31, warp = tid >> 5;
    int wm = warp >> 1, wn = warp & 1;      // 4x2 warp grid
    int gid = lane >> 2, tig = lane & 3;
    int mBase = blockIdx.y * BM;
    int nBase = blockIdx.x * BN;

    float acc[2][8][4];
    #pragma unroll
    for (int i=0;i<2;i++)
      #pragma unroll
      for (int j=0;j<8;j++)
        #pragma unroll
        for (int k=0;k<4;k++) acc[i][j][k]=0.f;

    auto load_stage = [&](int s, int kb){
        float* Asb = As + s*BM*SA_ST;
        float* Bsb = Bs + s*BK*SB_ST;
        #pragma unroll
        for (int it=0; it<4; it++){
            int id = it*256 + tid;
            int ar = id >> 3, k4 = id & 7;
            int row = mBase + ar;
            const float* src; int sz = 16;
            if (GATHER==1){
                int t = row >> 13, b = row & 8191;
                int idx = __ldg(seqs + b*7 + 2*t);
                src = table + (size_t)idx*256 + kb*BK + k4*4;
            } else {
                if (row < M) src = A + (size_t)row*256 + kb*BK + k4*4;
                else { src = A; sz = 0; }
            }
            cp16(Asb + ar*SA_ST + k4*4, src, sz);
        }
        #pragma unroll
        for (int it=0; it<4; it++){
            int id = it*256 + tid;
            int kr = id >> 5, n4 = id & 31;
            const float* src = W + (size_t)(kb*BK + kr)*N + nBase + n4*4;
            cp16(Bsb + kr*SB_ST + n4*4, src, 16);
        }
        cp_commit();
    };

    load_stage(0, 0);

    for (int kb=0; kb<8; kb++){
        int s = kb & 1;
        if (kb < 7){ load_stage(s^1, kb+1); cp_wait<1>(); }
        else       { cp_wait<0>(); }
        __syncthreads();

        const float* Ab = As + s*BM*SA_ST + (wm*32)*SA_ST;
        const float* Bb = Bs + s*BK*SB_ST + wn*64;
        #pragma unroll
        for (int kk=0; kk<4; kk++){
            uint32_t ah[2][4], al[2][4];
            #pragma unroll
            for (int mt=0; mt<2; mt++){
                const float* ap = Ab + (mt*16+gid)*SA_ST + kk*8 + tig;
                split_tf(ap[0],           ah[mt][0], al[mt][0]);
                split_tf(ap[8*SA_ST],     ah[mt][1], al[mt][1]);
                split_tf(ap[4],           ah[mt][2], al[mt][2]);
                split_tf(ap[8*SA_ST+4],   ah[mt][3], al[mt][3]);
            }
            uint32_t bh[8][2], bl[8][2];
            #pragma unroll
            for (int nt=0; nt<8; nt++){
                const float* bp = Bb + (kk*8+tig)*SB_ST + nt*8 + gid;
                split_tf(bp[0],        bh[nt][0], bl[nt][0]);
                split_tf(bp[4*SB_ST],  bh[nt][1], bl[nt][1]);
            }
            #pragma unroll
            for (int mt=0; mt<2; mt++)
              #pragma unroll
              for (int nt=0; nt<8; nt++){
                  mma8(acc[mt][nt], ah[mt], bh[nt]);
                  mma8(acc[mt][nt], ah[mt], bl[nt]);
                  mma8(acc[mt][nt], al[mt], bh[nt]);
              }
        }
        __syncthreads();
    }

    // epilogue: optional bias add, optional elementwise multiply by mulsrc
    #pragma unroll
    for (int mt=0; mt<2; mt++){
        #pragma unroll
        for (int nt=0; nt<8; nt++){
            int col = nBase + wn*64 + nt*8 + 2*tig;
            float bv0=0.f, bv1=0.f;
            if (bias){ bv0 = __ldg(bias+col); bv1 = __ldg(bias+col+1); }
            #pragma unroll
            for (int hf=0; hf<2; hf++){
                int row = mBase + wm*32 + mt*16 + gid + hf*8;
                if (row < M){
                    float v0 = acc[mt][nt][hf*2+0] + bv0;
                    float v1 = acc[mt][nt][hf*2+1] + bv1;
                    if (mulsrc){
                        v0 *= __ldg(mulsrc + (size_t)row*N + col);
                        v1 *= __ldg(mulsrc + (size_t)row*N + col + 1);
                    }
                    *(float2*)(C + (size_t)row*N + col) = make_float2(v0, v1);
                }
            }
        }
    }
}

// ---------------- fused gate/activation elementwise ----------------
__device__ __forceinline__ float sigm(float x){ return 1.f/(1.f + expf(-x)); }

__global__ void step_elem(const int* __restrict__ seqs, int t, int relofs)
{
    int b = blockIdx.x*4 + (threadIdx.x>>6);
    int j = (threadIdx.x & 63) * 4;
    int ridx = __ldg(seqs + b*7 + 2*t + 1) + relofs;
    if (ridx >= RELN) ridx -= RELN;
    const float* HQ  = g_HQ + (size_t)b*1024;
    const float* SAr = g_SA + ((size_t)t*8192 + b)*512;
    const float* RT  = g_RelTab + (size_t)ridx*512;

    float4 h2 = *(const float4*)(HQ + j);
    float4 x2 = *(const float4*)(HQ + 256 + j);
    float4 C1 = *(const float4*)(HQ + 512 + j);
    float4 C2 = *(const float4*)(HQ + 768 + j);
    float4 x1 = *(const float4*)(SAr + j);
    float4 Ag = *(const float4*)(SAr + 256 + j);
    float4 h4 = *(const float4*)(RT + j);
    float4 Bm = *(const float4*)(RT + 256 + j);
    float4 bg1 = *(const float4*)(g_bgc1 + j);
    float4 bg2 = *(const float4*)(g_bgc2 + j);
    float4 o1, o2;
    #define DOC(c) { \
        float g1v = sigm(Ag.c + C1.c + bg1.c); \
        o1.c = tanhf(g1v*h2.c + (1.f-g1v)*x1.c); \
        float g2v = sigm(C2.c + Bm.c + bg2.c); \
        o2.c = sigm(g2v*h4.c + (1.f-g2v)*x2.c); }
    DOC(x) DOC(y) DOC(z) DOC(w)
    #undef DOC
    *(float4*)(g_op1  + (size_t)b*256 + j) = o1;
    *(float4*)(g_hbuf + (size_t)b*256 + j) = o2;
}

// ---------------- embedding row gather ----------------
// rows r in [0,M): t = r>>13, b = r&8191, idx = seqs[b*7 + colbase + 2t]
__global__ void gather_rows(const float* __restrict__ table, const int* __restrict__ seqs,
                            int colbase, float* __restrict__ out, int M)
{
    int r = blockIdx.x*4 + (threadIdx.x>>6);
    if (r >= M) return;
    int t = r >> 13, b = r & 8191;
    int idx = __ldg(seqs + b*7 + colbase + 2*t);
    int j = (threadIdx.x & 63) * 4;
    float4 v = *(const float4*)(table + (size_t)idx*256 + j);
    *(float4*)(out + (size_t)r*256 + j) = v;
}

// ---------------- launch ----------------
extern "C" void kernel_launch(void* const* d_in, const int* in_sizes, int n_in,
                              void* d_out, int out_size)
{
    const int*   seqs      = (const int*)d_in[0];
    const float* sub_embed = (const float*)d_in[1];
    const float* rel_embed = (const float*)d_in[2];
    const float* obj_embed = (const float*)d_in[3];
    const float* W1 = (const float*)d_in[4];
    const float* W2 = (const float*)d_in[5];
    const float* b2 = (const float*)d_in[6];
    const float* W3 = (const float*)d_in[7];
    const float* W4 = (const float*)d_in[8];
    const float* b4 = (const float*)d_in[9];
    const float* W5 = (const float*)d_in[10];
    const float* W6 = (const float*)d_in[11];
    const float* b6 = (const float*)d_in[12];
    const float* Wg = (const float*)d_in[13];
    const float* bg = (const float*)d_in[14];
    float* out = (float*)d_out;

    cudaFuncSetAttribute(gemm_tf32<0>, cudaFuncAttributeMaxDynamicSharedMemorySize, SMEM_BYTES);
    cudaFuncSetAttribute(gemm_tf32<1>, cudaFuncAttributeMaxDynamicSharedMemorySize, SMEM_BYTES);

    float *pWsub,*pWrel,*pWh,*pbrel,*pbh,*pRelTab,*pSA,*pHQ,*pop1,*pP,*ph;
    cudaGetSymbolAddress((void**)&pWsub,   g_Wsub);
    cudaGetSymbolAddress((void**)&pWrel,   g_Wrel);
    cudaGetSymbolAddress((void**)&pWh,     g_Wh);
    cudaGetSymbolAddress((void**)&pbrel,   g_brel);
    cudaGetSymbolAddress((void**)&pbh,     g_bh);
    cudaGetSymbolAddress((void**)&pRelTab, g_RelTab);
    cudaGetSymbolAddress((void**)&pSA,     g_SA);
    cudaGetSymbolAddress((void**)&pHQ,     g_HQ);
    cudaGetSymbolAddress((void**)&pop1,    g_op1);
    cudaGetSymbolAddress((void**)&pP,      g_P);
    cudaGetSymbolAddress((void**)&ph,      g_hbuf);

    // 1) fold weights:  [W1|W1*WgT], [W4|W4*WgB], [W2|W3|W2*WgB|W3*WgT], gate biases
    combine_weights<<<dim3(8,8,8), dim3(32,32)>>>(W1,W2,W3,W4,Wg);
    bias_combine<<<1,256>>>(b2,b4,bg,Wg);

    // 2) rel table: only 2000 distinct rel rows -> precompute [h4 | Bm] per rel id
    gemm_tf32<0><<<dim3(4,16), 256, SMEM_BYTES>>>(rel_embed, nullptr, nullptr,
                                                  pWrel, pbrel, nullptr, pRelTab, RELN, 512);

    // 3) obj outputs (pure gathers)
    gather_rows<<<24576/4, 256>>>(obj_embed, seqs, 2, out + (size_t)2*OUTQ, 24576);
    gather_rows<<<24576/4, 256>>>(sub_embed, seqs, 2, out + (size_t)3*OUTQ, 24576);

    // 4) both directions
    for (int d=0; d<2; d++){
        const float* table = (d==0) ? sub_embed : obj_embed;
        // SA = gather(sub) @ [W1 | W1*WgT], for all 3 timesteps (t-major rows)
        gemm_tf32<1><<<dim3(4,192), 256, SMEM_BYTES>>>(nullptr, seqs, table,
                                                       pWsub, nullptr, nullptr, pSA, 24576, 512);
        // h0 = table[seqs[:,0]]
        gather_rows<<<8192/4, 256>>>(table, seqs, 0, ph, 8192);

        for (int t=0; t<TT; t++){
            // HQ = h @ [W2 | W3 | W2*WgB | W3*WgT] + [b2|0|0|0]
            gemm_tf32<0><<<dim3(8,64), 256, SMEM_BYTES>>>(ph, nullptr, nullptr,
                                                          pWh, pbh, nullptr, pHQ, 8192, 1024);
            // gates + activations -> op1, op2(=new h)
            step_elem<<<8192/4, 256>>>(seqs, t, (d==0)?0:1000);
            // P = op1 @ W5
            gemm_tf32<0><<<dim3(2,64), 256, SMEM_BYTES>>>(pop1, nullptr, nullptr,
                                                          W5, nullptr, nullptr, pP, 8192, 256);
            // out = P * (op2 @ W6 + b6)
            gemm_tf32<0><<<dim3(2,64), 256, SMEM_BYTES>>>(ph, nullptr, nullptr,
                                                          W6, b6, pP,
                                                          out + (size_t)d*OUTQ + (size_t)t*8192*256,
                                                          8192, 256);
        }
    }
}